// round 2
// baseline (speedup 1.0000x reference)
#include <cuda_runtime.h>
#include <cuda_bf16.h>
#include <stdint.h>

// Problem constants
#define BB   16
#define CC   256
#define HH   64
#define WW   64
#define HWD  (HH*WW)          // 4096
#define NQ   (BB*HWD)         // 65536 query vectors
#define KK   1024             // codebook size
#define ZQ_ELEMS ((size_t)BB*CC*HWD)   // 16777216

// Main kernel tiling
#define TN 64       // queries per block
#define TK 128      // codes per k-tile
#define TC 32       // c-chunk for B double buffer
#define NKT (KK/TK) // 8 k-tiles

// Scratch (device globals — no allocation allowed in kernel_launch)
__device__ float  g_cbT[CC * KK];     // codebook transposed [c][k]
__device__ float  g_cnorm[KK];        // ||c_k||^2
__device__ int    g_idx[NQ];          // argmin indices
__device__ double g_losssum;          // sum of (zq - zc)^2

// ---------- packed f32x2 helpers ----------
__device__ __forceinline__ unsigned long long pk2(float lo, float hi) {
    unsigned long long r;
    asm("mov.b64 %0, {%1, %2};" : "=l"(r) : "f"(lo), "f"(hi));
    return r;
}
__device__ __forceinline__ void upk2(unsigned long long v, float& lo, float& hi) {
    asm("mov.b64 {%0, %1}, %2;" : "=f"(lo), "=f"(hi) : "l"(v));
}
__device__ __forceinline__ void ffma2(unsigned long long& d, unsigned long long a,
                                      unsigned long long b) {
    asm("fma.rn.f32x2 %0, %1, %2, %0;" : "+l"(d) : "l"(a), "l"(b));
}

// ---------- prep: transpose codebook, compute ||c_k||^2 ----------
__global__ void prep_transpose(const float* __restrict__ cb) {
    int i = blockIdx.x * 256 + threadIdx.x;           // 0..262143
    int c = i >> 10, k = i & 1023;
    g_cbT[i] = cb[k * CC + c];
}

__global__ void prep_cnorm(const float* __restrict__ cb) {
    int k = blockIdx.x * 256 + threadIdx.x;
    if (k < KK) {
        const float* r = cb + (size_t)k * CC;
        float s = 0.f;
        #pragma unroll 8
        for (int c = 0; c < CC; c++) s += r[c] * r[c];
        g_cnorm[k] = s;
    }
}

__global__ void zero_loss() { g_losssum = 0.0; }

// ---------- main: fused GEMM + argmin ----------
// Block: 256 threads = 16 ky-groups x 16 qy-groups.
// Thread owns 4 queries (qy*4+i) x 8 codes ({4ky..4ky+3} U {64+4ky..64+4ky+3})
// per k-tile, accumulated as 16 packed f32x2 accumulators.
__global__ __launch_bounds__(256, 2)
void vq_main(const float* __restrict__ z, float* __restrict__ outIdxF, int writeIdxF) {
    extern __shared__ float sm[];
    float* As   = sm;                    // [256 c][64 q]   65536 B
    float* Bs   = As + 256 * TN;         // [2][TC][128]    32768 B
    float* cns  = Bs + 2 * TC * TK;      // [128]
    float* zns  = cns + TK;              // [64]
    float* redD = zns + TN;              // [64][16]
    int*   redK = (int*)(redD + TN * 16);// [64][16]

    const int t   = threadIdx.x;
    const int ky  = t & 15;
    const int qy  = t >> 4;
    const int n0  = blockIdx.x * TN;
    const int b   = n0 >> 12;            // 4096 = H*W
    const int hw0 = n0 & 4095;
    const float* zb = z + (size_t)b * CC * HWD + hw0;

    // Load A tile: 256 c-rows x 64 floats, fully coalesced (w-contiguous).
    for (int i = t; i < 256 * (TN / 4); i += 256) {
        int c = i >> 4, lane = (i & 15) * 4;
        *(float4*)(As + c * TN + lane) =
            *(const float4*)(zb + (size_t)c * HWD + lane);
    }
    __syncthreads();

    // ||z||^2 per query (sequential over c, mimics reference sum)
    if (t < TN) {
        float s = 0.f;
        #pragma unroll 8
        for (int c = 0; c < 256; c++) { float v = As[c * TN + t]; s += v * v; }
        zns[t] = s;
    }

    float bd[4]; int bk[4];
    #pragma unroll
    for (int i = 0; i < 4; i++) { bd[i] = 3.4e38f; bk[i] = 0; }

    for (int kt = 0; kt < NKT; kt++) {
        if (t < TK) cns[t] = g_cnorm[kt * TK + t];
        const float* cbtile = g_cbT + kt * TK;   // row stride KK

        unsigned long long acc[4][4];
        #pragma unroll
        for (int i = 0; i < 4; i++)
            #pragma unroll
            for (int j = 0; j < 4; j++) acc[i][j] = 0ULL;

        // preload chunk 0
        for (int i = t; i < TC * (TK / 4); i += 256) {   // 1024 float4
            int r = i >> 5, col = (i & 31) * 4;
            *(float4*)(Bs + r * TK + col) =
                *(const float4*)(cbtile + (size_t)r * KK + col);
        }
        __syncthreads();

        int buf = 0;
        for (int ch = 0; ch < 256 / TC; ch++) {
            // prefetch next chunk into registers
            float4 pf[4];
            if (ch < 256 / TC - 1) {
                int c0n = (ch + 1) * TC;
                #pragma unroll
                for (int p = 0; p < 4; p++) {
                    int i = t + p * 256;
                    int r = i >> 5, col = (i & 31) * 4;
                    pf[p] = *(const float4*)(cbtile + (size_t)(c0n + r) * KK + col);
                }
            }
            const int c0 = ch * TC;
            const float* bsb = Bs + buf * TC * TK;
            #pragma unroll 4
            for (int cc = 0; cc < TC; cc++) {
                int c = c0 + cc;
                float4 a  = *(const float4*)(As + c * TN + qy * 4);
                float4 b0 = *(const float4*)(bsb + cc * TK + ky * 4);
                float4 b1 = *(const float4*)(bsb + cc * TK + 64 + ky * 4);
                unsigned long long bp[4] = { pk2(b0.x, b0.y), pk2(b0.z, b0.w),
                                             pk2(b1.x, b1.y), pk2(b1.z, b1.w) };
                float av[4] = { a.x, a.y, a.z, a.w };
                #pragma unroll
                for (int i = 0; i < 4; i++) {
                    unsigned long long ad = pk2(av[i], av[i]);
                    #pragma unroll
                    for (int j = 0; j < 4; j++) ffma2(acc[i][j], ad, bp[j]);
                }
            }
            __syncthreads();
            if (ch < 256 / TC - 1) {
                float* bsn = Bs + (buf ^ 1) * TC * TK;
                #pragma unroll
                for (int p = 0; p < 4; p++) {
                    int i = t + p * 256;
                    int r = i >> 5, col = (i & 31) * 4;
                    *(float4*)(bsn + r * TK + col) = pf[p];
                }
                buf ^= 1;
                __syncthreads();
            }
        }

        // epilogue: d = (||z||^2 + ||c||^2) - 2*dot, argmin ascending-k
        #pragma unroll
        for (int i = 0; i < 4; i++) {
            float zn = zns[qy * 4 + i];
            #pragma unroll
            for (int j = 0; j < 4; j++) {
                float lo, hi;
                upk2(acc[i][j], lo, hi);
                int kl = (j < 2) ? (4 * ky + 2 * j) : (64 + 4 * ky + 2 * (j - 2));
                float dl = (zn + cns[kl])     - 2.0f * lo;
                float dh = (zn + cns[kl + 1]) - 2.0f * hi;
                int kg = kt * TK + kl;
                if (dl < bd[i]) { bd[i] = dl; bk[i] = kg; }
                if (dh < bd[i]) { bd[i] = dh; bk[i] = kg + 1; }
            }
        }
        __syncthreads();
    }

    // cross-thread reduction per query (16 candidates, tie -> smallest k)
    #pragma unroll
    for (int i = 0; i < 4; i++) {
        redD[(qy * 4 + i) * 16 + ky] = bd[i];
        redK[(qy * 4 + i) * 16 + ky] = bk[i];
    }
    __syncthreads();
    if (t < TN) {
        float bdq = redD[t * 16]; int bkq = redK[t * 16];
        #pragma unroll
        for (int y = 1; y < 16; y++) {
            float d = redD[t * 16 + y]; int k = redK[t * 16 + y];
            if (d < bdq || (d == bdq && k < bkq)) { bdq = d; bkq = k; }
        }
        g_idx[n0 + t] = bkq;
        if (writeIdxF) outIdxF[n0 + t] = (float)bkq;
    }
}

// ---------- writer: zq in NCHW + loss sum ----------
__global__ void vq_writer(const float* __restrict__ z, float* __restrict__ out) {
    __shared__ float warpsum[8];
    size_t base = (size_t)blockIdx.x * 2048;
    float s = 0.f;
    #pragma unroll
    for (int e = 0; e < 8; e++) {
        size_t idx = base + (size_t)e * 256 + threadIdx.x;
        int c  = (int)((idx >> 12) & 255);
        int n  = (int)(((idx >> 20) << 12) | (idx & 4095));  // b*4096 + hw
        int k  = g_idx[n];
        float v  = g_cbT[c * KK + k];
        float zv = z[idx];
        out[idx] = v;
        float d = v - zv;
        s += d * d;
    }
    // warp then block reduce
    #pragma unroll
    for (int o = 16; o > 0; o >>= 1) s += __shfl_down_sync(0xffffffffu, s, o);
    if ((threadIdx.x & 31) == 0) warpsum[threadIdx.x >> 5] = s;
    __syncthreads();
    if (threadIdx.x == 0) {
        float bs = 0.f;
        #pragma unroll
        for (int w = 0; w < 8; w++) bs += warpsum[w];
        atomicAdd(&g_losssum, (double)bs);
    }
}

__global__ void vq_finalize(float* __restrict__ outLoss) {
    double m = g_losssum / (double)ZQ_ELEMS;
    float mf = (float)m;
    *outLoss = mf - 0.25f * mf;   // mean1 - BETA*mean2 (identical values)
}

// ---------- launch ----------
extern "C" void kernel_launch(void* const* d_in, const int* in_sizes, int n_in,
                              void* d_out, int out_size) {
    const float* z  = (const float*)d_in[0];
    const float* cb = (const float*)d_in[1];
    if (n_in >= 2 && in_sizes[0] == KK * CC && in_sizes[1] == (int)ZQ_ELEMS) {
        z = (const float*)d_in[1]; cb = (const float*)d_in[0];
    }
    float* out = (float*)d_out;

    static const size_t SMEM_MAIN =
        (256 * TN + 2 * TC * TK + TK + TN + TN * 16) * sizeof(float)
        + TN * 16 * sizeof(int);
    cudaFuncSetAttribute(vq_main, cudaFuncAttributeMaxDynamicSharedMemorySize,
                         (int)SMEM_MAIN);

    prep_transpose<<<(CC * KK) / 256, 256>>>(cb);
    prep_cnorm<<<(KK + 255) / 256, 256>>>(cb);
    zero_loss<<<1, 1>>>();

    int writeIdxF = (out_size >= (int)(ZQ_ELEMS + NQ)) ? 1 : 0;
    float* outIdxF = out + ZQ_ELEMS;
    vq_main<<<NQ / TN, 256, SMEM_MAIN>>>(z, outIdxF, writeIdxF);

    vq_writer<<<(int)(ZQ_ELEMS / 2048), 256>>>(z, out);

    if (out_size >= (int)(ZQ_ELEMS + NQ + 1)) {
        vq_finalize<<<1, 1>>>(out + ZQ_ELEMS + NQ);
    }
}

// round 3
// speedup vs baseline: 1.0470x; 1.0470x over previous
#include <cuda_runtime.h>
#include <cuda_bf16.h>
#include <stdint.h>

// Problem constants
#define BB   16
#define CC   256
#define HH   64
#define WW   64
#define HWD  (HH*WW)          // 4096
#define NQ   (BB*HWD)         // 65536 query vectors
#define KK   1024             // codebook size
#define ZQ_ELEMS ((size_t)BB*CC*HWD)   // 16777216

// Main kernel tiling: block = 64 queries x 256 codes per k-tile, 4 k-tiles.
// Thread tile: 4 queries x 16 codes (32 FFMA2 per c-iter).
#define TN  64       // queries per block
#define TKT 256      // codes per k-tile
#define TC  16       // c-chunk for B double buffer
#define NKT (KK/TKT) // 4 k-tiles

// Scratch (device globals — no allocation allowed in kernel_launch)
__device__ float  g_cbT[CC * KK];     // codebook transposed [c][k]
__device__ float  g_cnorm[KK];        // ||c_k||^2
__device__ int    g_idx[NQ];          // argmin indices
__device__ double g_losssum;          // sum of (zq - zc)^2

// ---------- packed f32x2 helpers ----------
__device__ __forceinline__ unsigned long long pk2(float lo, float hi) {
    unsigned long long r;
    asm("mov.b64 %0, {%1, %2};" : "=l"(r) : "f"(lo), "f"(hi));
    return r;
}
__device__ __forceinline__ void upk2(unsigned long long v, float& lo, float& hi) {
    asm("mov.b64 {%0, %1}, %2;" : "=f"(lo), "=f"(hi) : "l"(v));
}
__device__ __forceinline__ void ffma2(unsigned long long& d, unsigned long long a,
                                      unsigned long long b) {
    asm("fma.rn.f32x2 %0, %1, %2, %0;" : "+l"(d) : "l"(a), "l"(b));
}

// ---------- prep: transpose codebook, compute ||c_k||^2 ----------
__global__ void prep_transpose(const float* __restrict__ cb) {
    int i = blockIdx.x * 256 + threadIdx.x;           // 0..262143
    int c = i >> 10, k = i & 1023;
    g_cbT[i] = cb[k * CC + c];
}

__global__ void prep_cnorm(const float* __restrict__ cb) {
    int k = blockIdx.x * 256 + threadIdx.x;
    if (k < KK) {
        const float* r = cb + (size_t)k * CC;
        float s = 0.f;
        #pragma unroll 8
        for (int c = 0; c < CC; c++) s += r[c] * r[c];
        g_cnorm[k] = s;
    }
}

__global__ void zero_loss() { g_losssum = 0.0; }

// ---------- main: fused GEMM + argmin ----------
// 256 threads = 16 ky x 16 qy. Thread owns queries {qy*4+i} and codes
// {g*64 + 4*ky + 0..3} for g=0..3 within each 256-code k-tile.
__global__ __launch_bounds__(256)
void vq_main(const float* __restrict__ z, float* __restrict__ outIdxF, int writeIdxF) {
    extern __shared__ float sm[];
    float* As   = sm;                    // [256 c][64 q]    65536 B
    float* Bs   = As + 256 * TN;         // [2][TC][256]     32768 B
    float* cns  = Bs + 2 * TC * TKT;     // [256]
    float* zns  = cns + TKT;             // [64]
    // reduction arrays alias Bs after the k-loop (Bs dead by then)
    float* redD = Bs;                    // [64][16]
    int*   redK = (int*)(Bs + TN * 16);  // [64][16]

    const int t   = threadIdx.x;
    const int ky  = t & 15;
    const int qy  = t >> 4;
    const int n0  = blockIdx.x * TN;
    const int b   = n0 >> 12;            // 4096 = H*W
    const int hw0 = n0 & 4095;
    const float* zb = z + (size_t)b * CC * HWD + hw0;

    // Load A tile: 256 c-rows x 64 floats, fully coalesced (w-contiguous).
    for (int i = t; i < 256 * (TN / 4); i += 256) {
        int c = i >> 4, lane = (i & 15) * 4;
        *(float4*)(As + c * TN + lane) =
            *(const float4*)(zb + (size_t)c * HWD + lane);
    }
    __syncthreads();

    // ||z||^2 per query
    if (t < TN) {
        float s = 0.f;
        #pragma unroll 8
        for (int c = 0; c < 256; c++) { float v = As[c * TN + t]; s += v * v; }
        zns[t] = s;
    }

    float bd[4]; int bk[4];
    #pragma unroll
    for (int i = 0; i < 4; i++) { bd[i] = 3.4e38f; bk[i] = 0; }

    for (int kt = 0; kt < NKT; kt++) {
        cns[t] = g_cnorm[kt * TKT + t];          // 256 threads, 256 entries
        const float* cbtile = g_cbT + kt * TKT;  // row stride KK

        // acc[i][j]: query qy*4+i, code-pair j -> codes g*64+4ky+{2*(j&1), +1}, g=j>>1
        unsigned long long acc[4][8];
        #pragma unroll
        for (int i = 0; i < 4; i++)
            #pragma unroll
            for (int j = 0; j < 8; j++) acc[i][j] = 0ULL;

        // preload chunk 0: TC rows x 256 floats = 1024 float4, 4 per thread
        #pragma unroll
        for (int p = 0; p < 4; p++) {
            int i = t + p * 256;
            int r = i >> 6, col = (i & 63) * 4;
            *(float4*)(Bs + r * TKT + col) =
                *(const float4*)(cbtile + (size_t)r * KK + col);
        }
        __syncthreads();

        int buf = 0;
        for (int ch = 0; ch < 256 / TC; ch++) {
            // prefetch next chunk into registers
            float4 pf[4];
            if (ch < 256 / TC - 1) {
                int c0n = (ch + 1) * TC;
                #pragma unroll
                for (int p = 0; p < 4; p++) {
                    int i = t + p * 256;
                    int r = i >> 6, col = (i & 63) * 4;
                    pf[p] = *(const float4*)(cbtile + (size_t)(c0n + r) * KK + col);
                }
            }
            const int c0 = ch * TC;
            const float* bsb = Bs + buf * TC * TKT;
            #pragma unroll 4
            for (int cc = 0; cc < TC; cc++) {
                int c = c0 + cc;
                float4 a  = *(const float4*)(As + c * TN + qy * 4);
                float4 b0 = *(const float4*)(bsb + cc * TKT +       ky * 4);
                float4 b1 = *(const float4*)(bsb + cc * TKT +  64 + ky * 4);
                float4 b2 = *(const float4*)(bsb + cc * TKT + 128 + ky * 4);
                float4 b3 = *(const float4*)(bsb + cc * TKT + 192 + ky * 4);
                unsigned long long bp[8] = {
                    pk2(b0.x, b0.y), pk2(b0.z, b0.w),
                    pk2(b1.x, b1.y), pk2(b1.z, b1.w),
                    pk2(b2.x, b2.y), pk2(b2.z, b2.w),
                    pk2(b3.x, b3.y), pk2(b3.z, b3.w) };
                float av[4] = { a.x, a.y, a.z, a.w };
                #pragma unroll
                for (int i = 0; i < 4; i++) {
                    unsigned long long ad = pk2(av[i], av[i]);
                    #pragma unroll
                    for (int j = 0; j < 8; j++) ffma2(acc[i][j], ad, bp[j]);
                }
            }
            __syncthreads();
            if (ch < 256 / TC - 1) {
                float* bsn = Bs + (buf ^ 1) * TC * TKT;
                #pragma unroll
                for (int p = 0; p < 4; p++) {
                    int i = t + p * 256;
                    int r = i >> 6, col = (i & 63) * 4;
                    *(float4*)(bsn + r * TKT + col) = pf[p];
                }
                buf ^= 1;
                __syncthreads();
            }
        }

        // epilogue: d = (||z||^2 + ||c||^2) - 2*dot, argmin ascending-k
        #pragma unroll
        for (int i = 0; i < 4; i++) {
            float zn = zns[qy * 4 + i];
            #pragma unroll
            for (int j = 0; j < 8; j++) {
                float lo, hi;
                upk2(acc[i][j], lo, hi);
                int kl = (j >> 1) * 64 + 4 * ky + 2 * (j & 1);
                float dl = (zn + cns[kl])     - 2.0f * lo;
                float dh = (zn + cns[kl + 1]) - 2.0f * hi;
                int kg = kt * TKT + kl;
                if (dl < bd[i]) { bd[i] = dl; bk[i] = kg; }
                if (dh < bd[i]) { bd[i] = dh; bk[i] = kg + 1; }
            }
        }
        __syncthreads();   // protects cns overwrite next kt / Bs alias below
    }

    // cross-thread reduction per query (16 candidates, tie -> smallest k).
    // Candidates are disjoint code sets per ky, ascending-k handled by < cmp
    // plus k-tiebreak below.
    #pragma unroll
    for (int i = 0; i < 4; i++) {
        redD[(qy * 4 + i) * 16 + ky] = bd[i];
        redK[(qy * 4 + i) * 16 + ky] = bk[i];
    }
    __syncthreads();
    if (t < TN) {
        float bdq = redD[t * 16]; int bkq = redK[t * 16];
        #pragma unroll
        for (int y = 1; y < 16; y++) {
            float d = redD[t * 16 + y]; int k = redK[t * 16 + y];
            if (d < bdq || (d == bdq && k < bkq)) { bdq = d; bkq = k; }
        }
        g_idx[n0 + t] = bkq;
        if (writeIdxF) outIdxF[n0 + t] = (float)bkq;
    }
}

// ---------- writer: zq in NCHW + loss sum ----------
__global__ void vq_writer(const float* __restrict__ z, float* __restrict__ out) {
    __shared__ float warpsum[8];
    size_t base = (size_t)blockIdx.x * 2048;
    float s = 0.f;
    #pragma unroll
    for (int e = 0; e < 8; e++) {
        size_t idx = base + (size_t)e * 256 + threadIdx.x;
        int c  = (int)((idx >> 12) & 255);
        int n  = (int)(((idx >> 20) << 12) | (idx & 4095));  // b*4096 + hw
        int k  = g_idx[n];
        float v  = g_cbT[c * KK + k];
        float zv = z[idx];
        out[idx] = v;
        float d = v - zv;
        s += d * d;
    }
    #pragma unroll
    for (int o = 16; o > 0; o >>= 1) s += __shfl_down_sync(0xffffffffu, s, o);
    if ((threadIdx.x & 31) == 0) warpsum[threadIdx.x >> 5] = s;
    __syncthreads();
    if (threadIdx.x == 0) {
        float bs = 0.f;
        #pragma unroll
        for (int w = 0; w < 8; w++) bs += warpsum[w];
        atomicAdd(&g_losssum, (double)bs);
    }
}

__global__ void vq_finalize(float* __restrict__ outLoss) {
    double m = g_losssum / (double)ZQ_ELEMS;
    float mf = (float)m;
    *outLoss = mf - 0.25f * mf;   // mean1 - BETA*mean2 (identical values)
}

// ---------- launch ----------
extern "C" void kernel_launch(void* const* d_in, const int* in_sizes, int n_in,
                              void* d_out, int out_size) {
    const float* z  = (const float*)d_in[0];
    const float* cb = (const float*)d_in[1];
    if (n_in >= 2 && in_sizes[0] == KK * CC && in_sizes[1] == (int)ZQ_ELEMS) {
        z = (const float*)d_in[1]; cb = (const float*)d_in[0];
    }
    float* out = (float*)d_out;

    static const size_t SMEM_MAIN =
        (256 * TN + 2 * TC * TKT + TKT + TN) * sizeof(float);
    cudaFuncSetAttribute(vq_main, cudaFuncAttributeMaxDynamicSharedMemorySize,
                         (int)SMEM_MAIN);

    prep_transpose<<<(CC * KK) / 256, 256>>>(cb);
    prep_cnorm<<<(KK + 255) / 256, 256>>>(cb);
    zero_loss<<<1, 1>>>();

    int writeIdxF = (out_size >= (int)(ZQ_ELEMS + NQ)) ? 1 : 0;
    float* outIdxF = out + ZQ_ELEMS;
    vq_main<<<NQ / TN, 256, SMEM_MAIN>>>(z, outIdxF, writeIdxF);

    vq_writer<<<(int)(ZQ_ELEMS / 2048), 256>>>(z, out);

    if (out_size >= (int)(ZQ_ELEMS + NQ + 1)) {
        vq_finalize<<<1, 1>>>(out + ZQ_ELEMS + NQ);
    }
}